// round 10
// baseline (speedup 1.0000x reference)
#include <cuda_runtime.h>
#include <cuda_fp16.h>
#include <cstdint>
#include <math.h>

#define BDIM 4
#define NN   4096
#define DD   1536
#define HH   512
#define KA   8
#define MTOT (BDIM*NN)
#define R2   (400.0f*400.0f)
#define GRIDC 20
#define NCELL (GRIDC*GRIDC)
#define CAND_CAP 448
#define NL_CAP 256

// ---------------- static device scratch ----------------------------------
__device__ __align__(16) __half g_img [(size_t)MTOT*DD];
__device__ __align__(16) __half g_feat[(size_t)MTOT*HH];
__device__ __align__(16) __half g_agg [(size_t)MTOT*HH];
__device__ __align__(16) __half g_Wf[HH*DD];   // transposed [H][D]
__device__ __align__(16) __half g_Wg[HH*HH];   // transposed [H][H]
__device__ __align__(16) __half g_Ws[HH*HH];
__device__ __align__(16) float g_anorm_t[DD*KA];   // transposed [D][K]
__device__ float g_concept[BDIM*KA];
__device__ float g_latent[BDIM*HH];
// spatial bins
__device__ int g_bin_cnt[BDIM][NCELL];
__device__ int g_bin_start[BDIM][NCELL + 1];
__device__ int g_bin_ptr[BDIM][NCELL];
__device__ int g_sorted[BDIM][NN];

// ---------------- PTX helpers (sm_80-class only) --------------------------
__device__ __forceinline__ uint32_t smem_u32(const void* p) {
    uint32_t a;
    asm("{ .reg .u64 t; cvta.to.shared.u64 t, %1; cvt.u32.u64 %0, t; }" : "=r"(a) : "l"(p));
    return a;
}
__device__ __forceinline__ void cp_async16(uint32_t dst, const void* src) {
    asm volatile("cp.async.cg.shared.global [%0], [%1], 16;\n"
                 :: "r"(dst), "l"(__cvta_generic_to_global(src)) : "memory");
}
__device__ __forceinline__ void ldsm4(uint32_t* r, uint32_t addr) {
    asm volatile("ldmatrix.sync.aligned.m8n8.x4.shared.b16 {%0,%1,%2,%3}, [%4];"
                 : "=r"(r[0]), "=r"(r[1]), "=r"(r[2]), "=r"(r[3]) : "r"(addr));
}
__device__ __forceinline__ void mma16816(float* d, const uint32_t* a, const uint32_t* b) {
    asm volatile("mma.sync.aligned.m16n8k16.row.col.f32.f16.f16.f32 "
                 "{%0,%1,%2,%3}, {%4,%5,%6,%7}, {%8,%9}, {%0,%1,%2,%3};"
                 : "+f"(d[0]), "+f"(d[1]), "+f"(d[2]), "+f"(d[3])
                 : "r"(a[0]), "r"(a[1]), "r"(a[2]), "r"(a[3]), "r"(b[0]), "r"(b[1]));
}
__device__ __forceinline__ uint32_t swz(uint32_t o) { return o ^ ((o >> 3) & 0x70); }

__device__ __forceinline__ int cell_of(float2 p) {
    int cx = min(GRIDC - 1, max(0, (int)(p.x * (1.0f / 400.0f))));
    int cy = min(GRIDC - 1, max(0, (int)(p.y * (1.0f / 400.0f))));
    return cy * GRIDC + cx;
}

// ---------------- utility kernels ----------------------------------------
__global__ void zero_kernel() {
    int t = blockIdx.x * blockDim.x + threadIdx.x;
    if (t < BDIM*HH) g_latent[t] = 0.0f;
    if (t < BDIM*KA) g_concept[t] = 0.0f;
    if (t < BDIM*NCELL) ((int*)g_bin_cnt)[t] = 0;
}

__global__ void anchor_norm_kernel(const float* __restrict__ anchors) {
    int k = blockIdx.x, t = threadIdx.x;
    __shared__ float red[256];
    float s = 0.0f;
    for (int d = t; d < DD; d += 256) { float v = anchors[k*DD + d]; s += v*v; }
    red[t] = s; __syncthreads();
    for (int off = 128; off > 0; off >>= 1) { if (t < off) red[t] += red[t+off]; __syncthreads(); }
    float inv = 1.0f / fmaxf(sqrtf(red[0]), 1e-12f);
    for (int d = t; d < DD; d += 256) g_anorm_t[(size_t)d*KA + k] = anchors[k*DD + d] * inv;
}

// ---- binning: count / prefix / scatter -----------------------------------
__global__ void bin_count_kernel(const float* __restrict__ pos) {
    int i = blockIdx.x * 256 + threadIdx.x;   // 0..MTOT-1
    int b = i >> 12;
    float2 p = *(const float2*)&pos[(size_t)i * 2];
    atomicAdd(&g_bin_cnt[b][cell_of(p)], 1);
}
__global__ void bin_prefix_kernel() {
    int b = blockIdx.x;
    if (threadIdx.x == 0) {
        int s = 0;
        for (int c = 0; c < NCELL; c++) {
            g_bin_start[b][c] = s;
            g_bin_ptr[b][c] = s;
            s += g_bin_cnt[b][c];
        }
        g_bin_start[b][NCELL] = s;
    }
}
__global__ void bin_scatter_kernel(const float* __restrict__ pos) {
    int i = blockIdx.x * 256 + threadIdx.x;
    int b = i >> 12;
    float2 p = *(const float2*)&pos[(size_t)i * 2];
    int o = atomicAdd(&g_bin_ptr[b][cell_of(p)], 1);
    g_sorted[b][o] = i & (NN - 1);
}

// ---- fused: images -> fp16 + cosine concept scores -----------------------
__global__ __launch_bounds__(192) void conv_img_concept(const float* __restrict__ images) {
    int row = blockIdx.x, t = threadIdx.x;
    const float4* x4 = (const float4*)(images + (size_t)row * DD);
    const float4* an4 = (const float4*)g_anorm_t;   // [D][8] -> 2 float4 per d
    float ss = 0.0f;
    float dots[KA];
    #pragma unroll
    for (int k = 0; k < KA; k++) dots[k] = 0.0f;

    #pragma unroll
    for (int half = 0; half < 2; half++) {
        int idx = t + half * 192;
        float4 v = x4[idx];
        float vv[4] = {v.x, v.y, v.z, v.w};
        #pragma unroll
        for (int e = 0; e < 4; e++) {
            float val = vv[e];
            ss += val * val;
            int d = idx * 4 + e;
            float4 a0 = an4[d*2], a1 = an4[d*2 + 1];
            dots[0] += val*a0.x; dots[1] += val*a0.y; dots[2] += val*a0.z; dots[3] += val*a0.w;
            dots[4] += val*a1.x; dots[5] += val*a1.y; dots[6] += val*a1.z; dots[7] += val*a1.w;
        }
        __half2 p01 = __floats2half2_rn(vv[0], vv[1]);
        __half2 p23 = __floats2half2_rn(vv[2], vv[3]);
        ((uint2*)g_img)[(size_t)row * 384 + idx] =
            make_uint2(*(uint32_t*)&p01, *(uint32_t*)&p23);
    }

    #pragma unroll
    for (int off = 16; off > 0; off >>= 1) {
        ss += __shfl_down_sync(0xffffffffu, ss, off);
        #pragma unroll
        for (int k = 0; k < KA; k++) dots[k] += __shfl_down_sync(0xffffffffu, dots[k], off);
    }
    __shared__ float sred[6][KA + 1];
    int lane = t & 31, wid = t >> 5;
    if (lane == 0) {
        sred[wid][0] = ss;
        #pragma unroll
        for (int k = 0; k < KA; k++) sred[wid][k+1] = dots[k];
    }
    __syncthreads();
    if (t == 0) {
        float S = 0.0f, Dk[KA];
        #pragma unroll
        for (int k = 0; k < KA; k++) Dk[k] = 0.0f;
        #pragma unroll
        for (int w = 0; w < 6; w++) {
            S += sred[w][0];
            #pragma unroll
            for (int k = 0; k < KA; k++) Dk[k] += sred[w][k+1];
        }
        float inv = 1.0f / fmaxf(sqrtf(S), 1e-12f);
        int b = row >> 12;
        #pragma unroll
        for (int k = 0; k < KA; k++)
            atomicAdd(&g_concept[b*KA + k], Dk[k] * inv * (1.0f / NN));
    }
}

// ---- weight transpose via smem tile (coalesced both ways) ---------------
__global__ __launch_bounds__(256) void conv_wf_kernel(const float* __restrict__ W) {
    __shared__ float tile[32][33];
    int k0 = blockIdx.x * 32, n0 = blockIdx.y * 32;
    int tx = threadIdx.x & 31, ty = threadIdx.x >> 5;
    #pragma unroll
    for (int r = 0; r < 32; r += 8)
        tile[ty + r][tx] = W[(size_t)(k0 + ty + r) * HH + n0 + tx];
    __syncthreads();
    #pragma unroll
    for (int r = 0; r < 32; r += 8)
        g_Wf[(size_t)(n0 + ty + r) * DD + k0 + tx] = __float2half_rn(tile[tx][ty + r]);
}
__global__ __launch_bounds__(256) void conv_w2_kernel(const float* __restrict__ Wg,
                                                      const float* __restrict__ Ws) {
    __shared__ float tile[32][33];
    const float* W = blockIdx.z ? Ws : Wg;
    __half* O = blockIdx.z ? g_Ws : g_Wg;
    int k0 = blockIdx.x * 32, n0 = blockIdx.y * 32;
    int tx = threadIdx.x & 31, ty = threadIdx.x >> 5;
    #pragma unroll
    for (int r = 0; r < 32; r += 8)
        tile[ty + r][tx] = W[(size_t)(k0 + ty + r) * HH + n0 + tx];
    __syncthreads();
    #pragma unroll
    for (int r = 0; r < 32; r += 8)
        O[(size_t)(n0 + ty + r) * HH + k0 + tx] = __float2half_rn(tile[tx][ty + r]);
}

// ---------------- HMMA GEMM (fp16, single pass) ---------------------------
#define STAGE_BYTES 32768
#define SB_OFF 16384
#define COLSUM_OFF 65536
#define GEMM_SMEM  (65536 + 512)

template<int MODE>
__device__ __forceinline__ void get_chunk(int i, const __half*& A, const __half*& B, int& k0) {
    if (MODE == 0) {
        A = g_img; B = g_Wf; k0 = i * 64;
    } else {
        if (i < 8) { A = g_agg;  B = g_Wg; k0 = i * 64; }
        else       { A = g_feat; B = g_Ws; k0 = (i - 8) * 64; }
    }
}

template<int LDA, int LDB, int MODE>
__device__ __forceinline__ void load_chunk(int tid, int m0, int n0, int i, int s, uint32_t sbase) {
    const __half *A, *B; int k0;
    get_chunk<MODE>(i, A, B, k0);
    uint32_t sa = sbase + s * STAGE_BYTES;
    #pragma unroll
    for (int q = 0; q < 4; q++) {
        int e = q * 256 + tid;
        int row = e >> 3, kc = e & 7;
        cp_async16(sa + swz(row * 128 + kc * 16),
                   A + (size_t)(m0 + row) * LDA + k0 + kc * 8);
    }
    #pragma unroll
    for (int q = 0; q < 4; q++) {
        int e = q * 256 + tid;
        int row = e >> 3, kc = e & 7;
        cp_async16(sa + SB_OFF + swz(row * 128 + kc * 16),
                   B + (size_t)(n0 + row) * LDB + k0 + kc * 8);
    }
    asm volatile("cp.async.commit_group;\n" ::: "memory");
}

template<int NCHUNK, int LDA, int LDB, int MODE>
__global__ __launch_bounds__(256, 2) void gemm_kernel(
    const float* __restrict__ bias, const float* __restrict__ Wp,
    const float* __restrict__ pos)
{
    extern __shared__ char smem[];
    uint32_t sbase = smem_u32(smem);
    int tid = threadIdx.x;
    int wid = tid >> 5, lane = tid & 31;
    int m0 = blockIdx.x * 128;
    int n0 = blockIdx.y * 128;

    int warp_m = (wid >> 1) * 32;
    int warp_n = (wid & 1) * 64;

    int a_row  = warp_m + (lane & 15);
    int a_half = (lane >> 4) * 16;
    int b_row  = warp_n + (lane & 7) + ((lane >> 4) * 8);
    int b_half = ((lane >> 3) & 1) * 16;

    float acc[2][8][4];
    #pragma unroll
    for (int mt = 0; mt < 2; mt++)
        #pragma unroll
        for (int nt = 0; nt < 8; nt++)
            #pragma unroll
            for (int j = 0; j < 4; j++) acc[mt][nt][j] = 0.0f;

    if (MODE == 1) {
        for (int c = tid; c < 128; c += 256) *(float*)(smem + COLSUM_OFF + 4*c) = 0.0f;
    }
    __syncthreads();

    load_chunk<LDA,LDB,MODE>(tid, m0, n0, 0, 0, sbase);
    load_chunk<LDA,LDB,MODE>(tid, m0, n0, 1, 1, sbase);

    for (int i = 0; i < NCHUNK; i++) {
        int s = i & 1;
        if (i + 1 < NCHUNK) asm volatile("cp.async.wait_group 1;\n" ::: "memory");
        else                asm volatile("cp.async.wait_group 0;\n" ::: "memory");
        __syncthreads();
        uint32_t sa = sbase + s * STAGE_BYTES;
        #pragma unroll
        for (int ks = 0; ks < 4; ks++) {
            uint32_t afr[2][4], bfr[4][4];
            #pragma unroll
            for (int mt = 0; mt < 2; mt++)
                ldsm4(afr[mt], sa + swz((a_row + mt*16) * 128 + ks*32 + a_half));
            #pragma unroll
            for (int g = 0; g < 4; g++)
                ldsm4(bfr[g], sa + SB_OFF + swz((b_row + g*16) * 128 + ks*32 + b_half));
            #pragma unroll
            for (int mt = 0; mt < 2; mt++)
                #pragma unroll
                for (int g = 0; g < 4; g++) {
                    mma16816(acc[mt][2*g+0], afr[mt], &bfr[g][0]);
                    mma16816(acc[mt][2*g+1], afr[mt], &bfr[g][2]);
                }
        }
        __syncthreads();
        if (i + 2 < NCHUNK)
            load_chunk<LDA,LDB,MODE>(tid, m0, n0, i + 2, s, sbase);
    }

    int r0 = lane >> 2;
    int cp = (lane & 3) * 2;

    if (MODE == 0) {
        float cb[16], cwx[16], cwy[16];
        #pragma unroll
        for (int nt = 0; nt < 8; nt++) {
            int n = n0 + warp_n + nt*8 + cp;
            cb[2*nt]   = bias[n];   cb[2*nt+1]   = bias[n+1];
            cwx[2*nt]  = Wp[n];     cwx[2*nt+1]  = Wp[n+1];
            cwy[2*nt]  = Wp[HH+n];  cwy[2*nt+1]  = Wp[HH+n+1];
        }
        #pragma unroll
        for (int mt = 0; mt < 2; mt++) {
            #pragma unroll
            for (int half = 0; half < 2; half++) {
                int m = m0 + warp_m + mt*16 + r0 + half*8;
                float2 p = *(const float2*)&pos[(size_t)m * 2];
                #pragma unroll
                for (int nt = 0; nt < 8; nt++) {
                    int n = n0 + warp_n + nt*8 + cp;
                    float v0 = acc[mt][nt][2*half+0] + cb[2*nt]   + p.x*cwx[2*nt]   + p.y*cwy[2*nt];
                    float v1 = acc[mt][nt][2*half+1] + cb[2*nt+1] + p.x*cwx[2*nt+1] + p.y*cwy[2*nt+1];
                    __half2 hp = __floats2half2_rn(v0, v1);
                    *(uint32_t*)&g_feat[(size_t)m * HH + n] = *(uint32_t*)&hp;
                }
            }
        }
    } else {
        float* colsum = (float*)(smem + COLSUM_OFF);
        #pragma unroll
        for (int nt = 0; nt < 8; nt++) {
            float s0 = 0.0f, s1 = 0.0f;
            #pragma unroll
            for (int mt = 0; mt < 2; mt++) {
                s0 += fmaxf(acc[mt][nt][0], 0.0f) + fmaxf(acc[mt][nt][2], 0.0f);
                s1 += fmaxf(acc[mt][nt][1], 0.0f) + fmaxf(acc[mt][nt][3], 0.0f);
            }
            #pragma unroll
            for (int off = 4; off <= 16; off <<= 1) {
                s0 += __shfl_xor_sync(0xffffffffu, s0, off);
                s1 += __shfl_xor_sync(0xffffffffu, s1, off);
            }
            if (lane < 4) {
                int c = warp_n + nt*8 + lane*2;
                atomicAdd(&colsum[c], s0);
                atomicAdd(&colsum[c+1], s1);
            }
        }
        __syncthreads();
        int b = m0 >> 12;
        if (tid < 128) atomicAdd(&g_latent[b * HH + n0 + tid], colsum[tid]);
    }
}

// ---------------- cell-based radius aggregation ----------------------------
// one block per (cell, graph): stage 3x3-window candidates in smem, then per
// center node: one cooperative pass builds the neighbor list, then gather.
__global__ __launch_bounds__(256) void agg_cell_kernel(const float* __restrict__ pos) {
    int cell = blockIdx.x;
    int b    = blockIdx.y;
    int t    = threadIdx.x;
    int cs = g_bin_start[b][cell], ce = g_bin_start[b][cell + 1];
    if (cs == ce) return;

    __shared__ float2 cpos[CAND_CAP];
    __shared__ int    cidx[CAND_CAP];
    __shared__ int    nlist[NL_CAP];
    __shared__ int    ncnt;

    int cx = cell % GRIDC, cy = cell / GRIDC;
    const float2* P = (const float2*)pos + (size_t)b * NN;

    // stage candidates from the 3x3 window
    int base = 0;
    for (int wy = max(0, cy-1); wy <= min(GRIDC-1, cy+1); wy++) {
        for (int wx = max(0, cx-1); wx <= min(GRIDC-1, cx+1); wx++) {
            int wc = wy * GRIDC + wx;
            int s = g_bin_start[b][wc], e = g_bin_start[b][wc + 1];
            for (int k = s + t; k < e; k += 256) {
                int o = base + (k - s);
                if (o < CAND_CAP) {
                    int j = g_sorted[b][k];
                    cpos[o] = P[j];
                    cidx[o] = j;
                }
            }
            base += e - s;
        }
    }
    int ncand = min(base, CAND_CAP);
    __syncthreads();

    const uint32_t* fh = (const uint32_t*)g_feat + (size_t)b * NN * (HH/2);
    uint32_t*       ah = (uint32_t*)g_agg + (size_t)b * NN * (HH/2);

    for (int ci = cs; ci < ce; ci++) {
        int i = g_sorted[b][ci];
        float2 pi = P[i];
        if (t == 0) ncnt = 0;
        __syncthreads();
        for (int c = t; c < ncand; c += 256) {
            float dx = pi.x - cpos[c].x, dy = pi.y - cpos[c].y;
            if (dx*dx + dy*dy < R2 && cidx[c] != i) {
                int o = atomicAdd(&ncnt, 1);
                if (o < NL_CAP) nlist[o] = cidx[c];
            }
        }
        __syncthreads();
        int cnt = min(ncnt, NL_CAP);
        float2 acc = make_float2(0.0f, 0.0f);
        for (int l = 0; l < cnt; l++) {
            uint32_t hv = fh[(size_t)nlist[l] * (HH/2) + t];
            float2 v = __half22float2(*(__half2*)&hv);
            acc.x += fmaxf(v.x, 0.0f);
            acc.y += fmaxf(v.y, 0.0f);
        }
        float inv = 1.0f / fmaxf((float)cnt, 1.0f);
        __half2 o2 = __floats2half2_rn(acc.x * inv, acc.y * inv);
        ah[(size_t)i * (HH/2) + t] = *(uint32_t*)&o2;
        __syncthreads();
    }
}

// ---------------- finalize ------------------------------------------------
__global__ void finalize_kernel(float* __restrict__ out) {
    int t = blockIdx.x * blockDim.x + threadIdx.x;
    if (t >= BDIM * (HH + KA)) return;
    int b = t / (HH + KA), c = t % (HH + KA);
    out[t] = (c < HH) ? g_latent[b*HH + c] * (1.0f / NN)
                      : g_concept[b*KA + (c - HH)];
}

// ---------------- launch --------------------------------------------------
extern "C" void kernel_launch(void* const* d_in, const int* in_sizes, int n_in,
                              void* d_out, int out_size)
{
    const float* images    = (const float*)d_in[0];
    const float* positions = (const float*)d_in[1];
    const float* W_feat    = (const float*)d_in[2];
    const float* b_feat    = (const float*)d_in[3];
    const float* W_pos     = (const float*)d_in[4];
    const float* W_gnn     = (const float*)d_in[5];
    const float* W_self    = (const float*)d_in[6];
    const float* anchors   = (const float*)d_in[7];
    float* out = (float*)d_out;

    cudaFuncSetAttribute(gemm_kernel<24, DD, DD, 0>,
                         cudaFuncAttributeMaxDynamicSharedMemorySize, GEMM_SMEM);
    cudaFuncSetAttribute(gemm_kernel<16, HH, HH, 1>,
                         cudaFuncAttributeMaxDynamicSharedMemorySize, GEMM_SMEM);

    dim3 gg(MTOT/128, HH/128);
    zero_kernel<<<(BDIM*HH + 255)/256 + 6, 256>>>();
    anchor_norm_kernel<<<KA, 256>>>(anchors);
    bin_count_kernel<<<MTOT/256, 256>>>(positions);
    bin_prefix_kernel<<<BDIM, 32>>>();
    bin_scatter_kernel<<<MTOT/256, 256>>>(positions);
    conv_img_concept<<<MTOT, 192>>>(images);
    conv_wf_kernel<<<dim3(DD/32, HH/32), 256>>>(W_feat);
    conv_w2_kernel<<<dim3(HH/32, HH/32, 2), 256>>>(W_gnn, W_self);
    gemm_kernel<24, DD, DD, 0><<<gg, 256, GEMM_SMEM>>>(b_feat, W_pos, positions);
    agg_cell_kernel<<<dim3(NCELL, BDIM), 256>>>(positions);
    gemm_kernel<16, HH, HH, 1><<<gg, 256, GEMM_SMEM>>>(nullptr, nullptr, nullptr);
    finalize_kernel<<<(BDIM*(HH+KA) + 255)/256, 256>>>(out);
}

// round 12
// speedup vs baseline: 1.1114x; 1.1114x over previous
#include <cuda_runtime.h>
#include <cuda_fp16.h>
#include <cstdint>
#include <math.h>

#define BDIM 4
#define NN   4096
#define DD   1536
#define HH   512
#define KA   8
#define MTOT (BDIM*NN)
#define R2   (400.0f*400.0f)
#define GRIDC 20
#define NCELL (GRIDC*GRIDC)
#define NL_CAP 256
#define NPB 8

// ---------------- static device scratch ----------------------------------
__device__ __align__(16) __half g_img [(size_t)MTOT*DD];
__device__ __align__(16) __half g_feat[(size_t)MTOT*HH];
__device__ __align__(16) __half g_agg [(size_t)MTOT*HH];
__device__ __align__(16) __half g_Wf[HH*DD];   // transposed [H][D]
__device__ __align__(16) __half g_Wg[HH*HH];   // transposed [H][H]
__device__ __align__(16) __half g_Ws[HH*HH];
__device__ __align__(16) float g_anorm_t[DD*KA];   // transposed [D][K]
__device__ float g_concept[BDIM*KA];
__device__ float g_latent[BDIM*HH];
// spatial bins
__device__ int g_bin_cnt[BDIM][NCELL];
__device__ int g_bin_start[BDIM][NCELL + 1];
__device__ int g_bin_ptr[BDIM][NCELL];
__device__ int g_sorted[BDIM][NN];

// ---------------- PTX helpers (sm_80-class only) --------------------------
__device__ __forceinline__ uint32_t smem_u32(const void* p) {
    uint32_t a;
    asm("{ .reg .u64 t; cvta.to.shared.u64 t, %1; cvt.u32.u64 %0, t; }" : "=r"(a) : "l"(p));
    return a;
}
__device__ __forceinline__ void cp_async16(uint32_t dst, const void* src) {
    asm volatile("cp.async.cg.shared.global [%0], [%1], 16;\n"
                 :: "r"(dst), "l"(__cvta_generic_to_global(src)) : "memory");
}
__device__ __forceinline__ void ldsm4(uint32_t* r, uint32_t addr) {
    asm volatile("ldmatrix.sync.aligned.m8n8.x4.shared.b16 {%0,%1,%2,%3}, [%4];"
                 : "=r"(r[0]), "=r"(r[1]), "=r"(r[2]), "=r"(r[3]) : "r"(addr));
}
__device__ __forceinline__ void mma16816(float* d, const uint32_t* a, const uint32_t* b) {
    asm volatile("mma.sync.aligned.m16n8k16.row.col.f32.f16.f16.f32 "
                 "{%0,%1,%2,%3}, {%4,%5,%6,%7}, {%8,%9}, {%0,%1,%2,%3};"
                 : "+f"(d[0]), "+f"(d[1]), "+f"(d[2]), "+f"(d[3])
                 : "r"(a[0]), "r"(a[1]), "r"(a[2]), "r"(a[3]), "r"(b[0]), "r"(b[1]));
}
__device__ __forceinline__ uint32_t swz(uint32_t o) { return o ^ ((o >> 3) & 0x70); }

__device__ __forceinline__ int cell_of(float2 p) {
    int cx = min(GRIDC - 1, max(0, (int)(p.x * (1.0f / 400.0f))));
    int cy = min(GRIDC - 1, max(0, (int)(p.y * (1.0f / 400.0f))));
    return cy * GRIDC + cx;
}

// ---------------- utility kernels ----------------------------------------
__global__ void zero_kernel() {
    int t = blockIdx.x * blockDim.x + threadIdx.x;
    if (t < BDIM*HH) g_latent[t] = 0.0f;
    if (t < BDIM*KA) g_concept[t] = 0.0f;
    if (t < BDIM*NCELL) ((int*)g_bin_cnt)[t] = 0;
}

__global__ void anchor_norm_kernel(const float* __restrict__ anchors) {
    int k = blockIdx.x, t = threadIdx.x;
    __shared__ float red[256];
    float s = 0.0f;
    for (int d = t; d < DD; d += 256) { float v = anchors[k*DD + d]; s += v*v; }
    red[t] = s; __syncthreads();
    for (int off = 128; off > 0; off >>= 1) { if (t < off) red[t] += red[t+off]; __syncthreads(); }
    float inv = 1.0f / fmaxf(sqrtf(red[0]), 1e-12f);
    for (int d = t; d < DD; d += 256) g_anorm_t[(size_t)d*KA + k] = anchors[k*DD + d] * inv;
}

// ---- binning: count / parallel prefix / scatter --------------------------
__global__ void bin_count_kernel(const float* __restrict__ pos) {
    int i = blockIdx.x * 256 + threadIdx.x;
    int b = i >> 12;
    float2 p = *(const float2*)&pos[(size_t)i * 2];
    atomicAdd(&g_bin_cnt[b][cell_of(p)], 1);
}
__global__ __launch_bounds__(512) void bin_prefix_kernel() {
    int b = blockIdx.x, t = threadIdx.x;
    __shared__ int s[NCELL];
    int cnt = 0;
    if (t < NCELL) { cnt = g_bin_cnt[b][t]; s[t] = cnt; }
    __syncthreads();
    #pragma unroll
    for (int off = 1; off < NCELL; off <<= 1) {
        int v = 0;
        if (t < NCELL && t >= off) v = s[t - off];
        __syncthreads();
        if (t < NCELL) s[t] += v;
        __syncthreads();
    }
    if (t < NCELL) {
        g_bin_start[b][t + 1] = s[t];
        g_bin_ptr[b][t] = s[t] - cnt;
    }
    if (t == 0) g_bin_start[b][0] = 0;
}
__global__ void bin_scatter_kernel(const float* __restrict__ pos) {
    int i = blockIdx.x * 256 + threadIdx.x;
    int b = i >> 12;
    float2 p = *(const float2*)&pos[(size_t)i * 2];
    int o = atomicAdd(&g_bin_ptr[b][cell_of(p)], 1);
    g_sorted[b][o] = i & (NN - 1);
}

// ---- fused: images -> fp16 + cosine concept scores -----------------------
__global__ __launch_bounds__(192) void conv_img_concept(const float* __restrict__ images) {
    int row = blockIdx.x, t = threadIdx.x;
    const float4* x4 = (const float4*)(images + (size_t)row * DD);
    const float4* an4 = (const float4*)g_anorm_t;
    float ss = 0.0f;
    float dots[KA];
    #pragma unroll
    for (int k = 0; k < KA; k++) dots[k] = 0.0f;

    #pragma unroll
    for (int half = 0; half < 2; half++) {
        int idx = t + half * 192;
        float4 v = x4[idx];
        float vv[4] = {v.x, v.y, v.z, v.w};
        #pragma unroll
        for (int e = 0; e < 4; e++) {
            float val = vv[e];
            ss += val * val;
            int d = idx * 4 + e;
            float4 a0 = an4[d*2], a1 = an4[d*2 + 1];
            dots[0] += val*a0.x; dots[1] += val*a0.y; dots[2] += val*a0.z; dots[3] += val*a0.w;
            dots[4] += val*a1.x; dots[5] += val*a1.y; dots[6] += val*a1.z; dots[7] += val*a1.w;
        }
        __half2 p01 = __floats2half2_rn(vv[0], vv[1]);
        __half2 p23 = __floats2half2_rn(vv[2], vv[3]);
        ((uint2*)g_img)[(size_t)row * 384 + idx] =
            make_uint2(*(uint32_t*)&p01, *(uint32_t*)&p23);
    }

    #pragma unroll
    for (int off = 16; off > 0; off >>= 1) {
        ss += __shfl_down_sync(0xffffffffu, ss, off);
        #pragma unroll
        for (int k = 0; k < KA; k++) dots[k] += __shfl_down_sync(0xffffffffu, dots[k], off);
    }
    __shared__ float sred[6][KA + 1];
    int lane = t & 31, wid = t >> 5;
    if (lane == 0) {
        sred[wid][0] = ss;
        #pragma unroll
        for (int k = 0; k < KA; k++) sred[wid][k+1] = dots[k];
    }
    __syncthreads();
    if (t == 0) {
        float S = 0.0f, Dk[KA];
        #pragma unroll
        for (int k = 0; k < KA; k++) Dk[k] = 0.0f;
        #pragma unroll
        for (int w = 0; w < 6; w++) {
            S += sred[w][0];
            #pragma unroll
            for (int k = 0; k < KA; k++) Dk[k] += sred[w][k+1];
        }
        float inv = 1.0f / fmaxf(sqrtf(S), 1e-12f);
        int b = row >> 12;
        #pragma unroll
        for (int k = 0; k < KA; k++)
            atomicAdd(&g_concept[b*KA + k], Dk[k] * inv * (1.0f / NN));
    }
}

// ---- weight transpose via smem tile (coalesced both ways) ---------------
__global__ __launch_bounds__(256) void conv_wf_kernel(const float* __restrict__ W) {
    __shared__ float tile[32][33];
    int k0 = blockIdx.x * 32, n0 = blockIdx.y * 32;
    int tx = threadIdx.x & 31, ty = threadIdx.x >> 5;
    #pragma unroll
    for (int r = 0; r < 32; r += 8)
        tile[ty + r][tx] = W[(size_t)(k0 + ty + r) * HH + n0 + tx];
    __syncthreads();
    #pragma unroll
    for (int r = 0; r < 32; r += 8)
        g_Wf[(size_t)(n0 + ty + r) * DD + k0 + tx] = __float2half_rn(tile[tx][ty + r]);
}
__global__ __launch_bounds__(256) void conv_w2_kernel(const float* __restrict__ Wg,
                                                      const float* __restrict__ Ws) {
    __shared__ float tile[32][33];
    const float* W = blockIdx.z ? Ws : Wg;
    __half* O = blockIdx.z ? g_Ws : g_Wg;
    int k0 = blockIdx.x * 32, n0 = blockIdx.y * 32;
    int tx = threadIdx.x & 31, ty = threadIdx.x >> 5;
    #pragma unroll
    for (int r = 0; r < 32; r += 8)
        tile[ty + r][tx] = W[(size_t)(k0 + ty + r) * HH + n0 + tx];
    __syncthreads();
    #pragma unroll
    for (int r = 0; r < 32; r += 8)
        O[(size_t)(n0 + ty + r) * HH + k0 + tx] = __float2half_rn(tile[tx][ty + r]);
}

// ---------------- HMMA GEMM (fp16, single pass) ---------------------------
#define STAGE_BYTES 32768
#define SB_OFF 16384
#define COLSUM_OFF 65536
#define GEMM_SMEM  (65536 + 512)

template<int MODE>
__device__ __forceinline__ void get_chunk(int i, const __half*& A, const __half*& B, int& k0) {
    if (MODE == 0) {
        A = g_img; B = g_Wf; k0 = i * 64;
    } else {
        if (i < 8) { A = g_agg;  B = g_Wg; k0 = i * 64; }
        else       { A = g_feat; B = g_Ws; k0 = (i - 8) * 64; }
    }
}

template<int LDA, int LDB, int MODE>
__device__ __forceinline__ void load_chunk(int tid, int m0, int n0, int i, int s, uint32_t sbase) {
    const __half *A, *B; int k0;
    get_chunk<MODE>(i, A, B, k0);
    uint32_t sa = sbase + s * STAGE_BYTES;
    #pragma unroll
    for (int q = 0; q < 4; q++) {
        int e = q * 256 + tid;
        int row = e >> 3, kc = e & 7;
        cp_async16(sa + swz(row * 128 + kc * 16),
                   A + (size_t)(m0 + row) * LDA + k0 + kc * 8);
    }
    #pragma unroll
    for (int q = 0; q < 4; q++) {
        int e = q * 256 + tid;
        int row = e >> 3, kc = e & 7;
        cp_async16(sa + SB_OFF + swz(row * 128 + kc * 16),
                   B + (size_t)(n0 + row) * LDB + k0 + kc * 8);
    }
    asm volatile("cp.async.commit_group;\n" ::: "memory");
}

template<int NCHUNK, int LDA, int LDB, int MODE>
__global__ __launch_bounds__(256, 2) void gemm_kernel(
    const float* __restrict__ bias, const float* __restrict__ Wp,
    const float* __restrict__ pos)
{
    extern __shared__ char smem[];
    uint32_t sbase = smem_u32(smem);
    int tid = threadIdx.x;
    int wid = tid >> 5, lane = tid & 31;
    int m0 = blockIdx.x * 128;
    int n0 = blockIdx.y * 128;

    int warp_m = (wid >> 1) * 32;
    int warp_n = (wid & 1) * 64;

    int a_row  = warp_m + (lane & 15);
    int a_half = (lane >> 4) * 16;
    int b_row  = warp_n + (lane & 7) + ((lane >> 4) * 8);
    int b_half = ((lane >> 3) & 1) * 16;

    float acc[2][8][4];
    #pragma unroll
    for (int mt = 0; mt < 2; mt++)
        #pragma unroll
        for (int nt = 0; nt < 8; nt++)
            #pragma unroll
            for (int j = 0; j < 4; j++) acc[mt][nt][j] = 0.0f;

    if (MODE == 1) {
        for (int c = tid; c < 128; c += 256) *(float*)(smem + COLSUM_OFF + 4*c) = 0.0f;
    }
    __syncthreads();

    load_chunk<LDA,LDB,MODE>(tid, m0, n0, 0, 0, sbase);
    load_chunk<LDA,LDB,MODE>(tid, m0, n0, 1, 1, sbase);

    for (int i = 0; i < NCHUNK; i++) {
        int s = i & 1;
        if (i + 1 < NCHUNK) asm volatile("cp.async.wait_group 1;\n" ::: "memory");
        else                asm volatile("cp.async.wait_group 0;\n" ::: "memory");
        __syncthreads();
        uint32_t sa = sbase + s * STAGE_BYTES;
        #pragma unroll
        for (int ks = 0; ks < 4; ks++) {
            uint32_t afr[2][4], bfr[4][4];
            #pragma unroll
            for (int mt = 0; mt < 2; mt++)
                ldsm4(afr[mt], sa + swz((a_row + mt*16) * 128 + ks*32 + a_half));
            #pragma unroll
            for (int g = 0; g < 4; g++)
                ldsm4(bfr[g], sa + SB_OFF + swz((b_row + g*16) * 128 + ks*32 + b_half));
            #pragma unroll
            for (int mt = 0; mt < 2; mt++)
                #pragma unroll
                for (int g = 0; g < 4; g++) {
                    mma16816(acc[mt][2*g+0], afr[mt], &bfr[g][0]);
                    mma16816(acc[mt][2*g+1], afr[mt], &bfr[g][2]);
                }
        }
        __syncthreads();
        if (i + 2 < NCHUNK)
            load_chunk<LDA,LDB,MODE>(tid, m0, n0, i + 2, s, sbase);
    }

    int r0 = lane >> 2;
    int cp = (lane & 3) * 2;

    if (MODE == 0) {
        float cb[16], cwx[16], cwy[16];
        #pragma unroll
        for (int nt = 0; nt < 8; nt++) {
            int n = n0 + warp_n + nt*8 + cp;
            cb[2*nt]   = bias[n];   cb[2*nt+1]   = bias[n+1];
            cwx[2*nt]  = Wp[n];     cwx[2*nt+1]  = Wp[n+1];
            cwy[2*nt]  = Wp[HH+n];  cwy[2*nt+1]  = Wp[HH+n+1];
        }
        #pragma unroll
        for (int mt = 0; mt < 2; mt++) {
            #pragma unroll
            for (int half = 0; half < 2; half++) {
                int m = m0 + warp_m + mt*16 + r0 + half*8;
                float2 p = *(const float2*)&pos[(size_t)m * 2];
                #pragma unroll
                for (int nt = 0; nt < 8; nt++) {
                    int n = n0 + warp_n + nt*8 + cp;
                    float v0 = acc[mt][nt][2*half+0] + cb[2*nt]   + p.x*cwx[2*nt]   + p.y*cwy[2*nt];
                    float v1 = acc[mt][nt][2*half+1] + cb[2*nt+1] + p.x*cwx[2*nt+1] + p.y*cwy[2*nt+1];
                    __half2 hp = __floats2half2_rn(v0, v1);
                    *(uint32_t*)&g_feat[(size_t)m * HH + n] = *(uint32_t*)&hp;
                }
            }
        }
    } else {
        float* colsum = (float*)(smem + COLSUM_OFF);
        #pragma unroll
        for (int nt = 0; nt < 8; nt++) {
            float s0 = 0.0f, s1 = 0.0f;
            #pragma unroll
            for (int mt = 0; mt < 2; mt++) {
                s0 += fmaxf(acc[mt][nt][0], 0.0f) + fmaxf(acc[mt][nt][2], 0.0f);
                s1 += fmaxf(acc[mt][nt][1], 0.0f) + fmaxf(acc[mt][nt][3], 0.0f);
            }
            #pragma unroll
            for (int off = 4; off <= 16; off <<= 1) {
                s0 += __shfl_xor_sync(0xffffffffu, s0, off);
                s1 += __shfl_xor_sync(0xffffffffu, s1, off);
            }
            if (lane < 4) {
                int c = warp_n + nt*8 + lane*2;
                atomicAdd(&colsum[c], s0);
                atomicAdd(&colsum[c+1], s1);
            }
        }
        __syncthreads();
        int b = m0 >> 12;
        if (tid < 128) atomicAdd(&g_latent[b * HH + n0 + tid], colsum[tid]);
    }
}

// ---------------- binned radius aggregation --------------------------------
// 8 sorted (spatially adjacent) nodes per block; warp w builds node w's
// neighbor list by scanning only its 3x3 cell window (~92 candidates);
// then the whole block gathers features (rows L1/L2-hot due to overlap).
__global__ __launch_bounds__(256) void agg_kernel(const float* __restrict__ pos) {
    int b    = blockIdx.x >> 9;              // 512 blocks per graph
    int base = (blockIdx.x & 511) * NPB;     // position in sorted order
    int t = threadIdx.x;
    int wid = t >> 5, lane = t & 31;
    __shared__ int nlist[NPB][NL_CAP];
    __shared__ int ncnt[NPB];
    __shared__ int nidx[NPB];
    const float2* P = (const float2*)pos + (size_t)b * NN;

    if (t < NPB) { ncnt[t] = 0; nidx[t] = g_sorted[b][base + t]; }
    __syncthreads();

    // warp wid builds list for node wid
    {
        int i = nidx[wid];
        float2 pi = P[i];
        int cx = min(GRIDC - 1, max(0, (int)(pi.x * (1.0f / 400.0f))));
        int cy = min(GRIDC - 1, max(0, (int)(pi.y * (1.0f / 400.0f))));
        int x0 = max(0, cx-1), x1 = min(GRIDC-1, cx+1);
        int y0 = max(0, cy-1), y1 = min(GRIDC-1, cy+1);
        for (int wy = y0; wy <= y1; wy++) {
            int wc0 = wy * GRIDC + x0;
            int s = g_bin_start[b][wc0];
            int e = g_bin_start[b][wy * GRIDC + x1 + 1];   // contiguous row segment
            for (int k = s + lane; k < e; k += 32) {
                int j = g_sorted[b][k];
                float2 pj = P[j];
                float dx = pi.x - pj.x, dy = pi.y - pj.y;
                if (dx*dx + dy*dy < R2 && j != i) {
                    int o = atomicAdd(&ncnt[wid], 1);
                    if (o < NL_CAP) nlist[wid][o] = j;
                }
            }
        }
    }
    __syncthreads();

    const uint32_t* fh = (const uint32_t*)g_feat + (size_t)b * NN * (HH/2);
    uint32_t*       ah = (uint32_t*)g_agg + (size_t)b * NN * (HH/2);
    #pragma unroll 1
    for (int u = 0; u < NPB; u++) {
        int cnt = min(ncnt[u], NL_CAP);
        float2 acc = make_float2(0.0f, 0.0f);
        for (int l = 0; l < cnt; l++) {
            uint32_t hv = fh[(size_t)nlist[u][l] * (HH/2) + t];
            float2 v = __half22float2(*(__half2*)&hv);
            acc.x += fmaxf(v.x, 0.0f);
            acc.y += fmaxf(v.y, 0.0f);
        }
        float inv = 1.0f / fmaxf((float)cnt, 1.0f);
        __half2 o2 = __floats2half2_rn(acc.x * inv, acc.y * inv);
        ah[(size_t)nidx[u] * (HH/2) + t] = *(uint32_t*)&o2;
    }
}

// ---------------- finalize ------------------------------------------------
__global__ void finalize_kernel(float* __restrict__ out) {
    int t = blockIdx.x * blockDim.x + threadIdx.x;
    if (t >= BDIM * (HH + KA)) return;
    int b = t / (HH + KA), c = t % (HH + KA);
    out[t] = (c < HH) ? g_latent[b*HH + c] * (1.0f / NN)
                      : g_concept[b*KA + (c - HH)];
}

// ---------------- launch --------------------------------------------------
extern "C" void kernel_launch(void* const* d_in, const int* in_sizes, int n_in,
                              void* d_out, int out_size)
{
    const float* images    = (const float*)d_in[0];
    const float* positions = (const float*)d_in[1];
    const float* W_feat    = (const float*)d_in[2];
    const float* b_feat    = (const float*)d_in[3];
    const float* W_pos     = (const float*)d_in[4];
    const float* W_gnn     = (const float*)d_in[5];
    const float* W_self    = (const float*)d_in[6];
    const float* anchors   = (const float*)d_in[7];
    float* out = (float*)d_out;

    cudaFuncSetAttribute(gemm_kernel<24, DD, DD, 0>,
                         cudaFuncAttributeMaxDynamicSharedMemorySize, GEMM_SMEM);
    cudaFuncSetAttribute(gemm_kernel<16, HH, HH, 1>,
                         cudaFuncAttributeMaxDynamicSharedMemorySize, GEMM_SMEM);

    dim3 gg(MTOT/128, HH/128);
    zero_kernel<<<(BDIM*HH + 255)/256 + 6, 256>>>();
    anchor_norm_kernel<<<KA, 256>>>(anchors);
    bin_count_kernel<<<MTOT/256, 256>>>(positions);
    bin_prefix_kernel<<<BDIM, 512>>>();
    bin_scatter_kernel<<<MTOT/256, 256>>>(positions);
    conv_img_concept<<<MTOT, 192>>>(images);
    conv_wf_kernel<<<dim3(DD/32, HH/32), 256>>>(W_feat);
    conv_w2_kernel<<<dim3(HH/32, HH/32, 2), 256>>>(W_gnn, W_self);
    gemm_kernel<24, DD, DD, 0><<<gg, 256, GEMM_SMEM>>>(b_feat, W_pos, positions);
    agg_kernel<<<MTOT/NPB, 256>>>(positions);
    gemm_kernel<16, HH, HH, 1><<<gg, 256, GEMM_SMEM>>>(nullptr, nullptr, nullptr);
    finalize_kernel<<<(BDIM*(HH+KA) + 255)/256, 256>>>(out);
}

// round 15
// speedup vs baseline: 1.1177x; 1.0057x over previous
#include <cuda_runtime.h>
#include <cuda_fp16.h>
#include <cstdint>
#include <math.h>

#define BDIM 4
#define NN   4096
#define DD   1536
#define HH   512
#define KA   8
#define MTOT (BDIM*NN)
#define R2   (400.0f*400.0f)
#define GRIDC 20
#define NCELL (GRIDC*GRIDC)
#define NL_CAP 256
#define NPB 8

// ---------------- static device scratch ----------------------------------
__device__ __align__(16) __half g_img [(size_t)MTOT*DD];
__device__ __align__(16) __half g_feat[(size_t)MTOT*HH];
__device__ __align__(16) __half g_agg [(size_t)MTOT*HH];
__device__ __align__(16) __half g_Wf[HH*DD];   // transposed [H][D]
__device__ __align__(16) __half g_Wg[HH*HH];   // transposed [H][H]
__device__ __align__(16) __half g_Ws[HH*HH];
__device__ __align__(16) float g_anorm_t[DD*KA];   // transposed [D][K]
__device__ float g_concept[BDIM*KA];
__device__ float g_latent[BDIM*HH];
// spatial bins
__device__ int g_bin_start[BDIM][NCELL + 1];
__device__ int g_sorted[BDIM][NN];

// ---------------- PTX helpers (sm_80-class only) --------------------------
__device__ __forceinline__ uint32_t smem_u32(const void* p) {
    uint32_t a;
    asm("{ .reg .u64 t; cvta.to.shared.u64 t, %1; cvt.u32.u64 %0, t; }" : "=r"(a) : "l"(p));
    return a;
}
__device__ __forceinline__ void cp_async16(uint32_t dst, const void* src) {
    asm volatile("cp.async.cg.shared.global [%0], [%1], 16;\n"
                 :: "r"(dst), "l"(__cvta_generic_to_global(src)) : "memory");
}
__device__ __forceinline__ void ldsm4(uint32_t* r, uint32_t addr) {
    asm volatile("ldmatrix.sync.aligned.m8n8.x4.shared.b16 {%0,%1,%2,%3}, [%4];"
                 : "=r"(r[0]), "=r"(r[1]), "=r"(r[2]), "=r"(r[3]) : "r"(addr));
}
__device__ __forceinline__ void mma16816(float* d, const uint32_t* a, const uint32_t* b) {
    asm volatile("mma.sync.aligned.m16n8k16.row.col.f32.f16.f16.f32 "
                 "{%0,%1,%2,%3}, {%4,%5,%6,%7}, {%8,%9}, {%0,%1,%2,%3};"
                 : "+f"(d[0]), "+f"(d[1]), "+f"(d[2]), "+f"(d[3])
                 : "r"(a[0]), "r"(a[1]), "r"(a[2]), "r"(a[3]), "r"(b[0]), "r"(b[1]));
}
__device__ __forceinline__ uint32_t swz(uint32_t o) { return o ^ ((o >> 3) & 0x70); }

__device__ __forceinline__ int cell_of(float2 p) {
    int cx = min(GRIDC - 1, max(0, (int)(p.x * (1.0f / 400.0f))));
    int cy = min(GRIDC - 1, max(0, (int)(p.y * (1.0f / 400.0f))));
    return cy * GRIDC + cx;
}

// ---------------- anchor normalize + zero accumulators --------------------
__global__ void anchor_norm_kernel(const float* __restrict__ anchors) {
    int k = blockIdx.x, t = threadIdx.x;
    int gid = k * 256 + t;
    if (gid < BDIM*HH) g_latent[gid] = 0.0f;
    if (gid < BDIM*KA) g_concept[gid] = 0.0f;
    __shared__ float red[256];
    float s = 0.0f;
    for (int d = t; d < DD; d += 256) { float v = anchors[k*DD + d]; s += v*v; }
    red[t] = s; __syncthreads();
    for (int off = 128; off > 0; off >>= 1) { if (t < off) red[t] += red[t+off]; __syncthreads(); }
    float inv = 1.0f / fmaxf(sqrtf(red[0]), 1e-12f);
    for (int d = t; d < DD; d += 256) g_anorm_t[(size_t)d*KA + k] = anchors[k*DD + d] * inv;
}

// ---- fused binning: count + prefix + scatter, one block per graph --------
__global__ __launch_bounds__(512) void bin_all_kernel(const float* __restrict__ pos) {
    int b = blockIdx.x, t = threadIdx.x;
    __shared__ int s[NCELL];
    __shared__ int sptr[NCELL];
    for (int c = t; c < NCELL; c += 512) s[c] = 0;
    __syncthreads();
    const float2* P = (const float2*)pos + (size_t)b * NN;
    int mycell[8];
    #pragma unroll
    for (int q = 0; q < 8; q++) {
        mycell[q] = cell_of(P[q * 512 + t]);
        atomicAdd(&s[mycell[q]], 1);
    }
    __syncthreads();
    int cnt = (t < NCELL) ? s[t] : 0;
    for (int off = 1; off < NCELL; off <<= 1) {
        int v = 0;
        if (t < NCELL && t >= off) v = s[t - off];
        __syncthreads();
        if (t < NCELL) s[t] += v;
        __syncthreads();
    }
    if (t < NCELL) {
        g_bin_start[b][t + 1] = s[t];
        sptr[t] = s[t] - cnt;
    }
    if (t == 0) g_bin_start[b][0] = 0;
    __syncthreads();
    #pragma unroll
    for (int q = 0; q < 8; q++) {
        int o = atomicAdd(&sptr[mycell[q]], 1);
        g_sorted[b][o] = q * 512 + t;
    }
}

// ---- fused: images -> fp16 + cosine concept scores -----------------------
__global__ __launch_bounds__(192) void conv_img_concept(const float* __restrict__ images) {
    int row = blockIdx.x, t = threadIdx.x;
    const float4* x4 = (const float4*)(images + (size_t)row * DD);
    const float4* an4 = (const float4*)g_anorm_t;
    float ss = 0.0f;
    float dots[KA];
    #pragma unroll
    for (int k = 0; k < KA; k++) dots[k] = 0.0f;

    #pragma unroll
    for (int half = 0; half < 2; half++) {
        int idx = t + half * 192;
        float4 v = x4[idx];
        float vv[4] = {v.x, v.y, v.z, v.w};
        #pragma unroll
        for (int e = 0; e < 4; e++) {
            float val = vv[e];
            ss += val * val;
            int d = idx * 4 + e;
            float4 a0 = an4[d*2], a1 = an4[d*2 + 1];
            dots[0] += val*a0.x; dots[1] += val*a0.y; dots[2] += val*a0.z; dots[3] += val*a0.w;
            dots[4] += val*a1.x; dots[5] += val*a1.y; dots[6] += val*a1.z; dots[7] += val*a1.w;
        }
        __half2 p01 = __floats2half2_rn(vv[0], vv[1]);
        __half2 p23 = __floats2half2_rn(vv[2], vv[3]);
        ((uint2*)g_img)[(size_t)row * 384 + idx] =
            make_uint2(*(uint32_t*)&p01, *(uint32_t*)&p23);
    }

    #pragma unroll
    for (int off = 16; off > 0; off >>= 1) {
        ss += __shfl_down_sync(0xffffffffu, ss, off);
        #pragma unroll
        for (int k = 0; k < KA; k++) dots[k] += __shfl_down_sync(0xffffffffu, dots[k], off);
    }
    __shared__ float sred[6][KA + 1];
    int lane = t & 31, wid = t >> 5;
    if (lane == 0) {
        sred[wid][0] = ss;
        #pragma unroll
        for (int k = 0; k < KA; k++) sred[wid][k+1] = dots[k];
    }
    __syncthreads();
    if (t == 0) {
        float S = 0.0f, Dk[KA];
        #pragma unroll
        for (int k = 0; k < KA; k++) Dk[k] = 0.0f;
        #pragma unroll
        for (int w = 0; w < 6; w++) {
            S += sred[w][0];
            #pragma unroll
            for (int k = 0; k < KA; k++) Dk[k] += sred[w][k+1];
        }
        float inv = 1.0f / fmaxf(sqrtf(S), 1e-12f);
        int b = row >> 12;
        #pragma unroll
        for (int k = 0; k < KA; k++)
            atomicAdd(&g_concept[b*KA + k], Dk[k] * inv * (1.0f / NN));
    }
}

// ---- weight transpose via smem tile (coalesced both ways) ---------------
__global__ __launch_bounds__(256) void conv_wf_kernel(const float* __restrict__ W) {
    __shared__ float tile[32][33];
    int k0 = blockIdx.x * 32, n0 = blockIdx.y * 32;
    int tx = threadIdx.x & 31, ty = threadIdx.x >> 5;
    #pragma unroll
    for (int r = 0; r < 32; r += 8)
        tile[ty + r][tx] = W[(size_t)(k0 + ty + r) * HH + n0 + tx];
    __syncthreads();
    #pragma unroll
    for (int r = 0; r < 32; r += 8)
        g_Wf[(size_t)(n0 + ty + r) * DD + k0 + tx] = __float2half_rn(tile[tx][ty + r]);
}
__global__ __launch_bounds__(256) void conv_w2_kernel(const float* __restrict__ Wg,
                                                      const float* __restrict__ Ws) {
    __shared__ float tile[32][33];
    const float* W = blockIdx.z ? Ws : Wg;
    __half* O = blockIdx.z ? g_Ws : g_Wg;
    int k0 = blockIdx.x * 32, n0 = blockIdx.y * 32;
    int tx = threadIdx.x & 31, ty = threadIdx.x >> 5;
    #pragma unroll
    for (int r = 0; r < 32; r += 8)
        tile[ty + r][tx] = W[(size_t)(k0 + ty + r) * HH + n0 + tx];
    __syncthreads();
    #pragma unroll
    for (int r = 0; r < 32; r += 8)
        O[(size_t)(n0 + ty + r) * HH + k0 + tx] = __float2half_rn(tile[tx][ty + r]);
}

// ---------------- HMMA GEMM (fp16, single pass) ---------------------------
#define STAGE_BYTES 32768
#define SB_OFF 16384
#define COLSUM_OFF 65536
#define GEMM_SMEM  (65536 + 512)

template<int MODE>
__device__ __forceinline__ void get_chunk(int i, const __half*& A, const __half*& B, int& k0) {
    if (MODE == 0) {
        A = g_img; B = g_Wf; k0 = i * 64;
    } else {
        if (i < 8) { A = g_agg;  B = g_Wg; k0 = i * 64; }
        else       { A = g_feat; B = g_Ws; k0 = (i - 8) * 64; }
    }
}

template<int LDA, int LDB, int MODE>
__device__ __forceinline__ void load_chunk(int tid, int m0, int n0, int i, int s, uint32_t sbase) {
    const __half *A, *B; int k0;
    get_chunk<MODE>(i, A, B, k0);
    uint32_t sa = sbase + s * STAGE_BYTES;
    #pragma unroll
    for (int q = 0; q < 4; q++) {
        int e = q * 256 + tid;
        int row = e >> 3, kc = e & 7;
        cp_async16(sa + swz(row * 128 + kc * 16),
                   A + (size_t)(m0 + row) * LDA + k0 + kc * 8);
    }
    #pragma unroll
    for (int q = 0; q < 4; q++) {
        int e = q * 256 + tid;
        int row = e >> 3, kc = e & 7;
        cp_async16(sa + SB_OFF + swz(row * 128 + kc * 16),
                   B + (size_t)(n0 + row) * LDB + k0 + kc * 8);
    }
    asm volatile("cp.async.commit_group;\n" ::: "memory");
}

template<int NCHUNK, int LDA, int LDB, int MODE>
__global__ __launch_bounds__(256, 2) void gemm_kernel(
    const float* __restrict__ bias, const float* __restrict__ Wp,
    const float* __restrict__ pos)
{
    extern __shared__ char smem[];
    uint32_t sbase = smem_u32(smem);
    int tid = threadIdx.x;
    int wid = tid >> 5, lane = tid & 31;
    int m0 = blockIdx.x * 128;
    int n0 = blockIdx.y * 128;

    int warp_m = (wid >> 1) * 32;
    int warp_n = (wid & 1) * 64;

    int a_row  = warp_m + (lane & 15);
    int a_half = (lane >> 4) * 16;
    int b_row  = warp_n + (lane & 7) + ((lane >> 4) * 8);
    int b_half = ((lane >> 3) & 1) * 16;

    float acc[2][8][4];
    #pragma unroll
    for (int mt = 0; mt < 2; mt++)
        #pragma unroll
        for (int nt = 0; nt < 8; nt++)
            #pragma unroll
            for (int j = 0; j < 4; j++) acc[mt][nt][j] = 0.0f;

    if (MODE == 1) {
        for (int c = tid; c < 128; c += 256) *(float*)(smem + COLSUM_OFF + 4*c) = 0.0f;
    }
    __syncthreads();

    load_chunk<LDA,LDB,MODE>(tid, m0, n0, 0, 0, sbase);
    load_chunk<LDA,LDB,MODE>(tid, m0, n0, 1, 1, sbase);

    for (int i = 0; i < NCHUNK; i++) {
        int s = i & 1;
        if (i + 1 < NCHUNK) asm volatile("cp.async.wait_group 1;\n" ::: "memory");
        else                asm volatile("cp.async.wait_group 0;\n" ::: "memory");
        __syncthreads();
        uint32_t sa = sbase + s * STAGE_BYTES;
        #pragma unroll
        for (int ks = 0; ks < 4; ks++) {
            uint32_t afr[2][4], bfr[4][4];
            #pragma unroll
            for (int mt = 0; mt < 2; mt++)
                ldsm4(afr[mt], sa + swz((a_row + mt*16) * 128 + ks*32 + a_half));
            #pragma unroll
            for (int g = 0; g < 4; g++)
                ldsm4(bfr[g], sa + SB_OFF + swz((b_row + g*16) * 128 + ks*32 + b_half));
            #pragma unroll
            for (int mt = 0; mt < 2; mt++)
                #pragma unroll
                for (int g = 0; g < 4; g++) {
                    mma16816(acc[mt][2*g+0], afr[mt], &bfr[g][0]);
                    mma16816(acc[mt][2*g+1], afr[mt], &bfr[g][2]);
                }
        }
        __syncthreads();
        if (i + 2 < NCHUNK)
            load_chunk<LDA,LDB,MODE>(tid, m0, n0, i + 2, s, sbase);
    }

    int r0 = lane >> 2;
    int cp = (lane & 3) * 2;

    if (MODE == 0) {
        float cb[16], cwx[16], cwy[16];
        #pragma unroll
        for (int nt = 0; nt < 8; nt++) {
            int n = n0 + warp_n + nt*8 + cp;
            cb[2*nt]   = bias[n];   cb[2*nt+1]   = bias[n+1];
            cwx[2*nt]  = Wp[n];     cwx[2*nt+1]  = Wp[n+1];
            cwy[2*nt]  = Wp[HH+n];  cwy[2*nt+1]  = Wp[HH+n+1];
        }
        #pragma unroll
        for (int mt = 0; mt < 2; mt++) {
            #pragma unroll
            for (int half = 0; half < 2; half++) {
                int m = m0 + warp_m + mt*16 + r0 + half*8;
                float2 p = *(const float2*)&pos[(size_t)m * 2];
                #pragma unroll
                for (int nt = 0; nt < 8; nt++) {
                    int n = n0 + warp_n + nt*8 + cp;
                    float v0 = acc[mt][nt][2*half+0] + cb[2*nt]   + p.x*cwx[2*nt]   + p.y*cwy[2*nt];
                    float v1 = acc[mt][nt][2*half+1] + cb[2*nt+1] + p.x*cwx[2*nt+1] + p.y*cwy[2*nt+1];
                    __half2 hp = __floats2half2_rn(v0, v1);
                    *(uint32_t*)&g_feat[(size_t)m * HH + n] = *(uint32_t*)&hp;
                }
            }
        }
    } else {
        float* colsum = (float*)(smem + COLSUM_OFF);
        #pragma unroll
        for (int nt = 0; nt < 8; nt++) {
            float s0 = 0.0f, s1 = 0.0f;
            #pragma unroll
            for (int mt = 0; mt < 2; mt++) {
                s0 += fmaxf(acc[mt][nt][0], 0.0f) + fmaxf(acc[mt][nt][2], 0.0f);
                s1 += fmaxf(acc[mt][nt][1], 0.0f) + fmaxf(acc[mt][nt][3], 0.0f);
            }
            #pragma unroll
            for (int off = 4; off <= 16; off <<= 1) {
                s0 += __shfl_xor_sync(0xffffffffu, s0, off);
                s1 += __shfl_xor_sync(0xffffffffu, s1, off);
            }
            if (lane < 4) {
                int c = warp_n + nt*8 + lane*2;
                atomicAdd(&colsum[c], s0);
                atomicAdd(&colsum[c+1], s1);
            }
        }
        __syncthreads();
        int b = m0 >> 12;
        if (tid < 128) atomicAdd(&g_latent[b * HH + n0 + tid], colsum[tid]);
    }
}

// ---------------- binned radius aggregation --------------------------------
__global__ __launch_bounds__(256) void agg_kernel(const float* __restrict__ pos) {
    int b    = blockIdx.x >> 9;              // 512 blocks per graph
    int base = (blockIdx.x & 511) * NPB;     // position in sorted order
    int t = threadIdx.x;
    int wid = t >> 5, lane = t & 31;
    __shared__ int nlist[NPB][NL_CAP];
    __shared__ int ncnt[NPB];
    __shared__ int nidx[NPB];
    const float2* P = (const float2*)pos + (size_t)b * NN;

    if (t < NPB) { ncnt[t] = 0; nidx[t] = g_sorted[b][base + t]; }
    __syncthreads();

    // warp wid builds list for node wid
    {
        int i = nidx[wid];
        float2 pi = P[i];
        int cx = min(GRIDC - 1, max(0, (int)(pi.x * (1.0f / 400.0f))));
        int cy = min(GRIDC - 1, max(0, (int)(pi.y * (1.0f / 400.0f))));
        int x0 = max(0, cx-1), x1 = min(GRIDC-1, cx+1);
        int y0 = max(0, cy-1), y1 = min(GRIDC-1, cy+1);
        for (int wy = y0; wy <= y1; wy++) {
            int s = g_bin_start[b][wy * GRIDC + x0];
            int e = g_bin_start[b][wy * GRIDC + x1 + 1];
            for (int k = s + lane; k < e; k += 32) {
                int j = g_sorted[b][k];
                float2 pj = P[j];
                float dx = pi.x - pj.x, dy = pi.y - pj.y;
                if (dx*dx + dy*dy < R2 && j != i) {
                    int o = atomicAdd(&ncnt[wid], 1);
                    if (o < NL_CAP) nlist[wid][o] = j;
                }
            }
        }
    }
    __syncthreads();

    const uint32_t* fh = (const uint32_t*)g_feat + (size_t)b * NN * (HH/2);
    uint32_t*       ah = (uint32_t*)g_agg + (size_t)b * NN * (HH/2);
    #pragma unroll 1
    for (int u = 0; u < NPB; u++) {
        int cnt = min(ncnt[u], NL_CAP);
        float2 acc = make_float2(0.0f, 0.0f);
        for (int l = 0; l < cnt; l++) {
            uint32_t hv = fh[(size_t)nlist[u][l] * (HH/2) + t];
            float2 v = __half22float2(*(__half2*)&hv);
            acc.x += fmaxf(v.x, 0.0f);
            acc.y += fmaxf(v.y, 0.0f);
        }
        float inv = 1.0f / fmaxf((float)cnt, 1.0f);
        __half2 o2 = __floats2half2_rn(acc.x * inv, acc.y * inv);
        ah[(size_t)nidx[u] * (HH/2) + t] = *(uint32_t*)&o2;
    }
}

// ---------------- finalize ------------------------------------------------
__global__ void finalize_kernel(float* __restrict__ out) {
    int t = blockIdx.x * blockDim.x + threadIdx.x;
    if (t >= BDIM * (HH + KA)) return;
    int b = t / (HH + KA), c = t % (HH + KA);
    out[t] = (c < HH) ? g_latent[b*HH + c] * (1.0f / NN)
                      : g_concept[b*KA + (c - HH)];
}

// ---------------- launch --------------------------------------------------
extern "C" void kernel_launch(void* const* d_in, const int* in_sizes, int n_in,
                              void* d_out, int out_size)
{
    const float* images    = (const float*)d_in[0];
    const float* positions = (const float*)d_in[1];
    const float* W_feat    = (const float*)d_in[2];
    const float* b_feat    = (const float*)d_in[3];
    const float* W_pos     = (const float*)d_in[4];
    const float* W_gnn     = (const float*)d_in[5];
    const float* W_self    = (const float*)d_in[6];
    const float* anchors   = (const float*)d_in[7];
    float* out = (float*)d_out;

    cudaFuncSetAttribute(gemm_kernel<24, DD, DD, 0>,
                         cudaFuncAttributeMaxDynamicSharedMemorySize, GEMM_SMEM);
    cudaFuncSetAttribute(gemm_kernel<16, HH, HH, 1>,
                         cudaFuncAttributeMaxDynamicSharedMemorySize, GEMM_SMEM);

    dim3 gg(MTOT/128, HH/128);
    // ncu profiles launch index 3 -> feat GEMM
    anchor_norm_kernel<<<KA, 256>>>(anchors);                                     // 0
    conv_img_concept<<<MTOT, 192>>>(images);                                      // 1
    conv_wf_kernel<<<dim3(DD/32, HH/32), 256>>>(W_feat);                          // 2
    gemm_kernel<24, DD, DD, 0><<<gg, 256, GEMM_SMEM>>>(b_feat, W_pos, positions); // 3 <- profiled
    bin_all_kernel<<<BDIM, 512>>>(positions);                                     // 4
    conv_w2_kernel<<<dim3(HH/32, HH/32, 2), 256>>>(W_gnn, W_self);                // 5
    agg_kernel<<<MTOT/NPB, 256>>>(positions);                                     // 6
    gemm_kernel<16, HH, HH, 1><<<gg, 256, GEMM_SMEM>>>(nullptr, nullptr, nullptr);// 7
    finalize_kernel<<<(BDIM*(HH+KA) + 255)/256, 256>>>(out);                      // 8
}

// round 17
// speedup vs baseline: 1.1271x; 1.0084x over previous
#include <cuda_runtime.h>
#include <cuda_fp16.h>
#include <cstdint>
#include <math.h>

#define BDIM 4
#define NN   4096
#define DD   1536
#define HH   512
#define KA   8
#define MTOT (BDIM*NN)
#define R2   (400.0f*400.0f)
#define GRIDC 20
#define NCELL (GRIDC*GRIDC)
#define NL_CAP 256
#define NPB 8

// ---------------- static device scratch ----------------------------------
__device__ __align__(16) __half g_img [(size_t)MTOT*DD];
__device__ __align__(16) __half g_feat[(size_t)MTOT*HH];
__device__ __align__(16) __half g_agg [(size_t)MTOT*HH];
__device__ __align__(16) __half g_Wf[HH*DD];   // transposed [H][D]
__device__ __align__(16) __half g_Wg[HH*HH];   // transposed [H][H]
__device__ __align__(16) __half g_Ws[HH*HH];
__device__ __align__(16) float g_anorm_t[DD*KA];   // transposed [D][K]
__device__ float g_concept[BDIM*KA];
__device__ float g_latent[BDIM*HH];
// spatial bins
__device__ int g_bin_start[BDIM][NCELL + 1];
__device__ int g_sorted[BDIM][NN];

// ---------------- PTX helpers (sm_80-class only) --------------------------
__device__ __forceinline__ uint32_t smem_u32(const void* p) {
    uint32_t a;
    asm("{ .reg .u64 t; cvta.to.shared.u64 t, %1; cvt.u32.u64 %0, t; }" : "=r"(a) : "l"(p));
    return a;
}
__device__ __forceinline__ void cp_async16(uint32_t dst, const void* src) {
    asm volatile("cp.async.cg.shared.global [%0], [%1], 16;\n"
                 :: "r"(dst), "l"(__cvta_generic_to_global(src)) : "memory");
}
__device__ __forceinline__ void ldsm4(uint32_t* r, uint32_t addr) {
    asm volatile("ldmatrix.sync.aligned.m8n8.x4.shared.b16 {%0,%1,%2,%3}, [%4];"
                 : "=r"(r[0]), "=r"(r[1]), "=r"(r[2]), "=r"(r[3]) : "r"(addr));
}
__device__ __forceinline__ void mma16816(float* d, const uint32_t* a, const uint32_t* b) {
    asm volatile("mma.sync.aligned.m16n8k16.row.col.f32.f16.f16.f32 "
                 "{%0,%1,%2,%3}, {%4,%5,%6,%7}, {%8,%9}, {%0,%1,%2,%3};"
                 : "+f"(d[0]), "+f"(d[1]), "+f"(d[2]), "+f"(d[3])
                 : "r"(a[0]), "r"(a[1]), "r"(a[2]), "r"(a[3]), "r"(b[0]), "r"(b[1]));
}
__device__ __forceinline__ uint32_t swz(uint32_t o) { return o ^ ((o >> 3) & 0x70); }

__device__ __forceinline__ int cell_of(float2 p) {
    int cx = min(GRIDC - 1, max(0, (int)(p.x * (1.0f / 400.0f))));
    int cy = min(GRIDC - 1, max(0, (int)(p.y * (1.0f / 400.0f))));
    return cy * GRIDC + cx;
}

// ---------------- anchor normalize + zero accumulators --------------------
__global__ void anchor_norm_kernel(const float* __restrict__ anchors) {
    int k = blockIdx.x, t = threadIdx.x;
    int gid = k * 256 + t;
    if (gid < BDIM*HH) g_latent[gid] = 0.0f;
    if (gid < BDIM*KA) g_concept[gid] = 0.0f;
    __shared__ float red[256];
    float s = 0.0f;
    for (int d = t; d < DD; d += 256) { float v = anchors[k*DD + d]; s += v*v; }
    red[t] = s; __syncthreads();
    for (int off = 128; off > 0; off >>= 1) { if (t < off) red[t] += red[t+off]; __syncthreads(); }
    float inv = 1.0f / fmaxf(sqrtf(red[0]), 1e-12f);
    for (int d = t; d < DD; d += 256) g_anorm_t[(size_t)d*KA + k] = anchors[k*DD + d] * inv;
}

// ---- fused binning: count + prefix + scatter, one block per graph --------
__global__ __launch_bounds__(512) void bin_all_kernel(const float* __restrict__ pos) {
    int b = blockIdx.x, t = threadIdx.x;
    __shared__ int s[NCELL];
    __shared__ int sptr[NCELL];
    for (int c = t; c < NCELL; c += 512) s[c] = 0;
    __syncthreads();
    const float2* P = (const float2*)pos + (size_t)b * NN;
    int mycell[8];
    #pragma unroll
    for (int q = 0; q < 8; q++) {
        mycell[q] = cell_of(P[q * 512 + t]);
        atomicAdd(&s[mycell[q]], 1);
    }
    __syncthreads();
    int cnt = (t < NCELL) ? s[t] : 0;
    for (int off = 1; off < NCELL; off <<= 1) {
        int v = 0;
        if (t < NCELL && t >= off) v = s[t - off];
        __syncthreads();
        if (t < NCELL) s[t] += v;
        __syncthreads();
    }
    if (t < NCELL) {
        g_bin_start[b][t + 1] = s[t];
        sptr[t] = s[t] - cnt;
    }
    if (t == 0) g_bin_start[b][0] = 0;
    __syncthreads();
    #pragma unroll
    for (int q = 0; q < 8; q++) {
        int o = atomicAdd(&sptr[mycell[q]], 1);
        g_sorted[b][o] = q * 512 + t;
    }
}

// ---- fused: images -> fp16 + cosine concept scores -----------------------
__global__ __launch_bounds__(192) void conv_img_concept(const float* __restrict__ images) {
    int row = blockIdx.x, t = threadIdx.x;
    const float4* x4 = (const float4*)(images + (size_t)row * DD);
    const float4* an4 = (const float4*)g_anorm_t;
    float ss = 0.0f;
    float dots[KA];
    #pragma unroll
    for (int k = 0; k < KA; k++) dots[k] = 0.0f;

    #pragma unroll
    for (int half = 0; half < 2; half++) {
        int idx = t + half * 192;
        float4 v = x4[idx];
        float vv[4] = {v.x, v.y, v.z, v.w};
        #pragma unroll
        for (int e = 0; e < 4; e++) {
            float val = vv[e];
            ss += val * val;
            int d = idx * 4 + e;
            float4 a0 = an4[d*2], a1 = an4[d*2 + 1];
            dots[0] += val*a0.x; dots[1] += val*a0.y; dots[2] += val*a0.z; dots[3] += val*a0.w;
            dots[4] += val*a1.x; dots[5] += val*a1.y; dots[6] += val*a1.z; dots[7] += val*a1.w;
        }
        __half2 p01 = __floats2half2_rn(vv[0], vv[1]);
        __half2 p23 = __floats2half2_rn(vv[2], vv[3]);
        ((uint2*)g_img)[(size_t)row * 384 + idx] =
            make_uint2(*(uint32_t*)&p01, *(uint32_t*)&p23);
    }

    #pragma unroll
    for (int off = 16; off > 0; off >>= 1) {
        ss += __shfl_down_sync(0xffffffffu, ss, off);
        #pragma unroll
        for (int k = 0; k < KA; k++) dots[k] += __shfl_down_sync(0xffffffffu, dots[k], off);
    }
    __shared__ float sred[6][KA + 1];
    int lane = t & 31, wid = t >> 5;
    if (lane == 0) {
        sred[wid][0] = ss;
        #pragma unroll
        for (int k = 0; k < KA; k++) sred[wid][k+1] = dots[k];
    }
    __syncthreads();
    if (t == 0) {
        float S = 0.0f, Dk[KA];
        #pragma unroll
        for (int k = 0; k < KA; k++) Dk[k] = 0.0f;
        #pragma unroll
        for (int w = 0; w < 6; w++) {
            S += sred[w][0];
            #pragma unroll
            for (int k = 0; k < KA; k++) Dk[k] += sred[w][k+1];
        }
        float inv = 1.0f / fmaxf(sqrtf(S), 1e-12f);
        int b = row >> 12;
        #pragma unroll
        for (int k = 0; k < KA; k++)
            atomicAdd(&g_concept[b*KA + k], Dk[k] * inv * (1.0f / NN));
    }
}

// ---- weight transpose via smem tile (coalesced both ways) ---------------
__global__ __launch_bounds__(256) void conv_wf_kernel(const float* __restrict__ W) {
    __shared__ float tile[32][33];
    int k0 = blockIdx.x * 32, n0 = blockIdx.y * 32;
    int tx = threadIdx.x & 31, ty = threadIdx.x >> 5;
    #pragma unroll
    for (int r = 0; r < 32; r += 8)
        tile[ty + r][tx] = W[(size_t)(k0 + ty + r) * HH + n0 + tx];
    __syncthreads();
    #pragma unroll
    for (int r = 0; r < 32; r += 8)
        g_Wf[(size_t)(n0 + ty + r) * DD + k0 + tx] = __float2half_rn(tile[tx][ty + r]);
}
__global__ __launch_bounds__(256) void conv_w2_kernel(const float* __restrict__ Wg,
                                                      const float* __restrict__ Ws) {
    __shared__ float tile[32][33];
    const float* W = blockIdx.z ? Ws : Wg;
    __half* O = blockIdx.z ? g_Ws : g_Wg;
    int k0 = blockIdx.x * 32, n0 = blockIdx.y * 32;
    int tx = threadIdx.x & 31, ty = threadIdx.x >> 5;
    #pragma unroll
    for (int r = 0; r < 32; r += 8)
        tile[ty + r][tx] = W[(size_t)(k0 + ty + r) * HH + n0 + tx];
    __syncthreads();
    #pragma unroll
    for (int r = 0; r < 32; r += 8)
        O[(size_t)(n0 + ty + r) * HH + k0 + tx] = __float2half_rn(tile[tx][ty + r]);
}

// ---------------- HMMA GEMM (fp16, 3-stage cp.async pipeline) --------------
#define STAGE_BYTES 32768
#define SB_OFF 16384
#define COLSUM_OFF 98304
#define GEMM_SMEM  (98304 + 512)

template<int MODE>
__device__ __forceinline__ void get_chunk(int i, const __half*& A, const __half*& B, int& k0) {
    if (MODE == 0) {
        A = g_img; B = g_Wf; k0 = i * 64;
    } else {
        if (i < 8) { A = g_agg;  B = g_Wg; k0 = i * 64; }
        else       { A = g_feat; B = g_Ws; k0 = (i - 8) * 64; }
    }
}

template<int LDA, int LDB, int MODE>
__device__ __forceinline__ void load_chunk(int tid, int m0, int n0, int i, int s, uint32_t sbase) {
    const __half *A, *B; int k0;
    get_chunk<MODE>(i, A, B, k0);
    uint32_t sa = sbase + s * STAGE_BYTES;
    #pragma unroll
    for (int q = 0; q < 4; q++) {
        int e = q * 256 + tid;
        int row = e >> 3, kc = e & 7;
        cp_async16(sa + swz(row * 128 + kc * 16),
                   A + (size_t)(m0 + row) * LDA + k0 + kc * 8);
    }
    #pragma unroll
    for (int q = 0; q < 4; q++) {
        int e = q * 256 + tid;
        int row = e >> 3, kc = e & 7;
        cp_async16(sa + SB_OFF + swz(row * 128 + kc * 16),
                   B + (size_t)(n0 + row) * LDB + k0 + kc * 8);
    }
    asm volatile("cp.async.commit_group;\n" ::: "memory");
}

template<int NCHUNK, int LDA, int LDB, int MODE>
__global__ __launch_bounds__(256, 2) void gemm_kernel(
    const float* __restrict__ bias, const float* __restrict__ Wp,
    const float* __restrict__ pos)
{
    extern __shared__ char smem[];
    uint32_t sbase = smem_u32(smem);
    int tid = threadIdx.x;
    int wid = tid >> 5, lane = tid & 31;
    int m0 = blockIdx.x * 128;
    int n0 = blockIdx.y * 128;

    int warp_m = (wid >> 1) * 32;
    int warp_n = (wid & 1) * 64;

    int a_row  = warp_m + (lane & 15);
    int a_half = (lane >> 4) * 16;
    int b_row  = warp_n + (lane & 7) + ((lane >> 4) * 8);
    int b_half = ((lane >> 3) & 1) * 16;

    float acc[2][8][4];
    #pragma unroll
    for (int mt = 0; mt < 2; mt++)
        #pragma unroll
        for (int nt = 0; nt < 8; nt++)
            #pragma unroll
            for (int j = 0; j < 4; j++) acc[mt][nt][j] = 0.0f;

    if (MODE == 1) {
        for (int c = tid; c < 128; c += 256) *(float*)(smem + COLSUM_OFF + 4*c) = 0.0f;
    }
    __syncthreads();

    load_chunk<LDA,LDB,MODE>(tid, m0, n0, 0, 0, sbase);
    load_chunk<LDA,LDB,MODE>(tid, m0, n0, 1, 1, sbase);

    int s_cur = 0;    // stage of chunk i
    int s_nxt = 2;    // stage for chunk i+2
    for (int i = 0; i < NCHUNK; i++) {
        if (i + 1 < NCHUNK) asm volatile("cp.async.wait_group 1;\n" ::: "memory");
        else                asm volatile("cp.async.wait_group 0;\n" ::: "memory");
        __syncthreads();   // single sync: stage s_cur visible; stage s_nxt free
        if (i + 2 < NCHUNK) {
            load_chunk<LDA,LDB,MODE>(tid, m0, n0, i + 2, s_nxt, sbase);
        }
        uint32_t sa = sbase + s_cur * STAGE_BYTES;
        #pragma unroll
        for (int ks = 0; ks < 4; ks++) {
            uint32_t afr[2][4], bfr[4][4];
            #pragma unroll
            for (int mt = 0; mt < 2; mt++)
                ldsm4(afr[mt], sa + swz((a_row + mt*16) * 128 + ks*32 + a_half));
            #pragma unroll
            for (int g = 0; g < 4; g++)
                ldsm4(bfr[g], sa + SB_OFF + swz((b_row + g*16) * 128 + ks*32 + b_half));
            #pragma unroll
            for (int mt = 0; mt < 2; mt++)
                #pragma unroll
                for (int g = 0; g < 4; g++) {
                    mma16816(acc[mt][2*g+0], afr[mt], &bfr[g][0]);
                    mma16816(acc[mt][2*g+1], afr[mt], &bfr[g][2]);
                }
        }
        s_cur = (s_cur == 2) ? 0 : s_cur + 1;
        s_nxt = (s_nxt == 2) ? 0 : s_nxt + 1;
    }

    int r0 = lane >> 2;
    int cp = (lane & 3) * 2;

    if (MODE == 0) {
        float cb[16], cwx[16], cwy[16];
        #pragma unroll
        for (int nt = 0; nt < 8; nt++) {
            int n = n0 + warp_n + nt*8 + cp;
            cb[2*nt]   = bias[n];   cb[2*nt+1]   = bias[n+1];
            cwx[2*nt]  = Wp[n];     cwx[2*nt+1]  = Wp[n+1];
            cwy[2*nt]  = Wp[HH+n];  cwy[2*nt+1]  = Wp[HH+n+1];
        }
        #pragma unroll
        for (int mt = 0; mt < 2; mt++) {
            #pragma unroll
            for (int half = 0; half < 2; half++) {
                int m = m0 + warp_m + mt*16 + r0 + half*8;
                float2 p = *(const float2*)&pos[(size_t)m * 2];
                #pragma unroll
                for (int nt = 0; nt < 8; nt++) {
                    int n = n0 + warp_n + nt*8 + cp;
                    float v0 = acc[mt][nt][2*half+0] + cb[2*nt]   + p.x*cwx[2*nt]   + p.y*cwy[2*nt];
                    float v1 = acc[mt][nt][2*half+1] + cb[2*nt+1] + p.x*cwx[2*nt+1] + p.y*cwy[2*nt+1];
                    __half2 hp = __floats2half2_rn(v0, v1);
                    *(uint32_t*)&g_feat[(size_t)m * HH + n] = *(uint32_t*)&hp;
                }
            }
        }
    } else {
        float* colsum = (float*)(smem + COLSUM_OFF);
        #pragma unroll
        for (int nt = 0; nt < 8; nt++) {
            float s0 = 0.0f, s1 = 0.0f;
            #pragma unroll
            for (int mt = 0; mt < 2; mt++) {
                s0 += fmaxf(acc[mt][nt][0], 0.0f) + fmaxf(acc[mt][nt][2], 0.0f);
                s1 += fmaxf(acc[mt][nt][1], 0.0f) + fmaxf(acc[mt][nt][3], 0.0f);
            }
            #pragma unroll
            for (int off = 4; off <= 16; off <<= 1) {
                s0 += __shfl_xor_sync(0xffffffffu, s0, off);
                s1 += __shfl_xor_sync(0xffffffffu, s1, off);
            }
            if (lane < 4) {
                int c = warp_n + nt*8 + lane*2;
                atomicAdd(&colsum[c], s0);
                atomicAdd(&colsum[c+1], s1);
            }
        }
        __syncthreads();
        int b = m0 >> 12;
        if (tid < 128) atomicAdd(&g_latent[b * HH + n0 + tid], colsum[tid]);
    }
}

// ---------------- binned radius aggregation --------------------------------
__global__ __launch_bounds__(256) void agg_kernel(const float* __restrict__ pos) {
    int b    = blockIdx.x >> 9;              // 512 blocks per graph
    int base = (blockIdx.x & 511) * NPB;     // position in sorted order
    int t = threadIdx.x;
    int wid = t >> 5, lane = t & 31;
    __shared__ int nlist[NPB][NL_CAP];
    __shared__ int ncnt[NPB];
    __shared__ int nidx[NPB];
    const float2* P = (const float2*)pos + (size_t)b * NN;

    if (t < NPB) { ncnt[t] = 0; nidx[t] = g_sorted[b][base + t]; }
    __syncthreads();

    // warp wid builds list for node wid
    {
        int i = nidx[wid];
        float2 pi = P[i];
        int cx = min(GRIDC - 1, max(0, (int)(pi.x * (1.0f / 400.0f))));
        int cy = min(GRIDC - 1, max(0, (int)(pi.y * (1.0f / 400.0f))));
        int x0 = max(0, cx-1), x1 = min(GRIDC-1, cx+1);
        int y0 = max(0, cy-1), y1 = min(GRIDC-1, cy+1);
        for (int wy = y0; wy <= y1; wy++) {
            int s = g_bin_start[b][wy * GRIDC + x0];
            int e = g_bin_start[b][wy * GRIDC + x1 + 1];
            for (int k = s + lane; k < e; k += 32) {
                int j = g_sorted[b][k];
                float2 pj = P[j];
                float dx = pi.x - pj.x, dy = pi.y - pj.y;
                if (dx*dx + dy*dy < R2 && j != i) {
                    int o = atomicAdd(&ncnt[wid], 1);
                    if (o < NL_CAP) nlist[wid][o] = j;
                }
            }
        }
    }
    __syncthreads();

    const uint32_t* fh = (const uint32_t*)g_feat + (size_t)b * NN * (HH/2);
    uint32_t*       ah = (uint32_t*)g_agg + (size_t)b * NN * (HH/2);
    #pragma unroll 1
    for (int u = 0; u < NPB; u++) {
        int cnt = min(ncnt[u], NL_CAP);
        float2 acc = make_float2(0.0f, 0.0f);
        for (int l = 0; l < cnt; l++) {
            uint32_t hv = fh[(size_t)nlist[u][l] * (HH/2) + t];
            float2 v = __half22float2(*(__half2*)&hv);
            acc.x += fmaxf(v.x, 0.0f);
            acc.y += fmaxf(v.y, 0.0f);
        }
        float inv = 1.0f / fmaxf((float)cnt, 1.0f);
        __half2 o2 = __floats2half2_rn(acc.x * inv, acc.y * inv);
        ah[(size_t)nidx[u] * (HH/2) + t] = *(uint32_t*)&o2;
    }
}

// ---------------- finalize ------------------------------------------------
__global__ void finalize_kernel(float* __restrict__ out) {
    int t = blockIdx.x * blockDim.x + threadIdx.x;
    if (t >= BDIM * (HH + KA)) return;
    int b = t / (HH + KA), c = t % (HH + KA);
    out[t] = (c < HH) ? g_latent[b*HH + c] * (1.0f / NN)
                      : g_concept[b*KA + (c - HH)];
}

// ---------------- launch --------------------------------------------------
extern "C" void kernel_launch(void* const* d_in, const int* in_sizes, int n_in,
                              void* d_out, int out_size)
{
    const float* images    = (const float*)d_in[0];
    const float* positions = (const float*)d_in[1];
    const float* W_feat    = (const float*)d_in[2];
    const float* b_feat    = (const float*)d_in[3];
    const float* W_pos     = (const float*)d_in[4];
    const float* W_gnn     = (const float*)d_in[5];
    const float* W_self    = (const float*)d_in[6];
    const float* anchors   = (const float*)d_in[7];
    float* out = (float*)d_out;

    cudaFuncSetAttribute(gemm_kernel<24, DD, DD, 0>,
                         cudaFuncAttributeMaxDynamicSharedMemorySize, GEMM_SMEM);
    cudaFuncSetAttribute(gemm_kernel<16, HH, HH, 1>,
                         cudaFuncAttributeMaxDynamicSharedMemorySize, GEMM_SMEM);

    dim3 gg(MTOT/128, HH/128);
    // ncu profiles launch index 3 -> feat GEMM
    anchor_norm_kernel<<<KA, 256>>>(anchors);                                     // 0
    conv_img_concept<<<MTOT, 192>>>(images);                                      // 1
    conv_wf_kernel<<<dim3(DD/32, HH/32), 256>>>(W_feat);                          // 2
    gemm_kernel<24, DD, DD, 0><<<gg, 256, GEMM_SMEM>>>(b_feat, W_pos, positions); // 3 <- profiled
    bin_all_kernel<<<BDIM, 512>>>(positions);                                     // 4
    conv_w2_kernel<<<dim3(HH/32, HH/32, 2), 256>>>(W_gnn, W_self);                // 5
    agg_kernel<<<MTOT/NPB, 256>>>(positions);                                     // 6
    gemm_kernel<16, HH, HH, 1><<<gg, 256, GEMM_SMEM>>>(nullptr, nullptr, nullptr);// 7
    finalize_kernel<<<(BDIM*(HH+KA) + 255)/256, 256>>>(out);                      // 8
}